// round 1
// baseline (speedup 1.0000x reference)
#include <cuda_runtime.h>
#include <stdint.h>

// out[n,o] = -|eta| * sum_i |x[n,i] - w[o,i]|
// N=2048, IN_F(K)=1024, OUT_F=2048, all fp32.
//
// Strategy: packed f32x2 adds (fma pipe) + LOP3 abs (alu pipe), GEMM-style
// smem tiling. Pack two consecutive k into one 64-bit lane; each output keeps
// a packed partial-sum pair folded in the epilogue.

#define N_ROWS 2048
#define K_DIM  1024
#define O_COLS 2048

#define TN 128   // block tile (n)
#define TO 64    // block tile (o)
#define KT 32    // k tile
#define SS 36    // smem row stride in floats (144B: 16B aligned, conflict-free)
#define RM 8     // outputs per thread (n)
#define RN 4     // outputs per thread (o)

__global__ __launch_bounds__(256, 2)
void adder_linear_kernel(const float* __restrict__ x,
                         const float* __restrict__ w,
                         const float* __restrict__ eta,
                         float* __restrict__ out)
{
    __shared__ float sx[TN * SS];   // 18KB
    __shared__ float sw[TO * SS];   // 9KB  (stores -w)

    const int tid    = threadIdx.x;
    const int wid    = tid >> 5;
    const int lane   = tid & 31;
    const int warp_n = wid & 1;          // 0..1  (64 n each)
    const int warp_o = wid >> 1;         // 0..3  (16 o each)
    const int lane_n = lane & 7;         // 0..7
    const int lane_o = lane >> 3;        // 0..3

    const int n0 = blockIdx.y * TN;
    const int o0 = blockIdx.x * TO;

    // thread-local tile coordinates: n = tn + i*8, o = to + j*4
    const int tn = warp_n * 64 + lane_n;
    const int to = warp_o * 16 + lane_o;

    uint64_t acc[RM][RN];
    #pragma unroll
    for (int i = 0; i < RM; i++)
        #pragma unroll
        for (int j = 0; j < RN; j++)
            acc[i][j] = 0ull;   // bit pattern 0 == (0.0f, 0.0f)

    for (int kt = 0; kt < K_DIM; kt += KT) {
        // ---- load x tile: 128 rows x 32 floats (float4 granularity) ----
        #pragma unroll
        for (int it = 0; it < 4; it++) {
            int idx = tid + 256 * it;           // 0..1023
            int r = idx >> 3, q = idx & 7;
            float4 v = *(const float4*)&x[(size_t)(n0 + r) * K_DIM + kt + q * 4];
            *(float4*)&sx[r * SS + q * 4] = v;
        }
        // ---- load w tile negated: 64 rows x 32 floats ----
        #pragma unroll
        for (int it = 0; it < 2; it++) {
            int idx = tid + 256 * it;           // 0..511
            int r = idx >> 3, q = idx & 7;
            float4 v = *(const float4*)&w[(size_t)(o0 + r) * K_DIM + kt + q * 4];
            v.x = -v.x; v.y = -v.y; v.z = -v.z; v.w = -v.w;
            *(float4*)&sw[r * SS + q * 4] = v;
        }
        __syncthreads();

        // ---- compute: 16 k-pairs ----
        #pragma unroll 4
        for (int kk = 0; kk < KT; kk += 2) {
            uint64_t xf[RM], wf[RN];
            #pragma unroll
            for (int i = 0; i < RM; i++)
                xf[i] = *(const uint64_t*)&sx[(tn + i * 8) * SS + kk];
            #pragma unroll
            for (int j = 0; j < RN; j++)
                wf[j] = *(const uint64_t*)&sw[(to + j * 4) * SS + kk];

            #pragma unroll
            for (int i = 0; i < RM; i++) {
                #pragma unroll
                for (int j = 0; j < RN; j++) {
                    uint64_t d;
                    // packed diff: (x_k0, x_k1) + (-w_k0, -w_k1)
                    asm("add.rn.f32x2 %0, %1, %2;"
                        : "=l"(d) : "l"(xf[i]), "l"(wf[j]));
                    // packed abs: clear sign bits of both halves (ALU pipe)
                    asm("{\n\t"
                        ".reg .b32 lo, hi;\n\t"
                        "mov.b64 {lo, hi}, %0;\n\t"
                        "and.b32 lo, lo, 0x7fffffff;\n\t"
                        "and.b32 hi, hi, 0x7fffffff;\n\t"
                        "mov.b64 %0, {lo, hi};\n\t"
                        "}" : "+l"(d));
                    // packed accumulate
                    asm("add.rn.f32x2 %0, %0, %1;"
                        : "+l"(acc[i][j]) : "l"(d));
                }
            }
        }
        __syncthreads();
    }

    const float scale = -fabsf(eta[0]);

    #pragma unroll
    for (int i = 0; i < RM; i++) {
        int n = n0 + tn + i * 8;
        #pragma unroll
        for (int j = 0; j < RN; j++) {
            int o = o0 + to + j * 4;
            float lo, hi;
            asm("mov.b64 {%0, %1}, %2;" : "=f"(lo), "=f"(hi) : "l"(acc[i][j]));
            out[(size_t)n * O_COLS + o] = (lo + hi) * scale;
        }
    }
}

extern "C" void kernel_launch(void* const* d_in, const int* in_sizes, int n_in,
                              void* d_out, int out_size)
{
    const float* x   = (const float*)d_in[0];   // [2048, 1024]
    const float* w   = (const float*)d_in[1];   // [2048, 1024]
    const float* eta = (const float*)d_in[2];   // [1]
    float* out = (float*)d_out;                 // [2048, 2048]

    dim3 grid(O_COLS / TO, N_ROWS / TN);        // (32, 16) = 512 blocks
    adder_linear_kernel<<<grid, 256>>>(x, w, eta, out);
}